// round 7
// baseline (speedup 1.0000x reference)
#include <cuda_runtime.h>
#include <cuda_bf16.h>

// RotaryPositionEncoding3D: out[B,N,192,2] f32 from xyz[B,N,3] f32 and div_term[32] f32.
// Each output float4 g = (cos, sin, cos, sin) of angle xyz[p, axis]*div_term[bin],
//   p = g/96, j = g%96, axis = j%3, bin = j/3.
//
// v6: PERSISTENT grid-stride version of the winning v2 body.
//  - 1184 blocks (148 SMs x 8 resident CTAs) x 256 threads, each block loops
//    over 1024-float4 tiles with stride gridDim.x (~21 tiles/block).
//    Eliminates ~20 wave transitions' worth of CTA launch/retire churn that
//    v2's 24576 short-lived blocks paid (occ was 87.6%, nothing saturated).
//  - per tile: closed-form independent per-k indices -> 4 front-batched
//    LDG+MUFU chains, then 4 __stcs STG.128 (512B contiguous per warp store).
//  - iterations independent (only loop-carried state = tile counter), so
//    cross-tile MLP overlaps stores with next tile's loads.
// 402.6 MB stored; effective 7.0 TB/s in v2 = 88% of HBM spec.

#define F4_PER_THREAD 4
#define THREADS 256
#define TILE (THREADS * F4_PER_THREAD)   // 1024 float4 per tile
#define MAX_BLOCKS (148 * 8)             // full residency on GB300 (152 SMs; 148 safe)

__global__ void __launch_bounds__(THREADS)
rope3d_kernel(const float* __restrict__ xyz,
              const float* __restrict__ div_term,
              float4* __restrict__ out,
              int num_tiles, int total_f4) {
    for (int tile = blockIdx.x; tile < num_tiles; tile += gridDim.x) {
        const int base = tile * TILE + (int)threadIdx.x;

        const unsigned p0 = (unsigned)base / 96u;
        const unsigned j0 = (unsigned)base - p0 * 96u;   // [0, 96)

        float c[F4_PER_THREAD], s[F4_PER_THREAD];

#pragma unroll
        for (int k = 0; k < F4_PER_THREAD; ++k) {
            // Independent per-k index math: t < 96 + 3*256 = 864
            unsigned t    = j0 + (unsigned)(k * THREADS);
            unsigned dp   = t / 96u;
            unsigned jk   = t - dp * 96u;                // j = 3*bin + axis
            unsigned bin  = jk / 3u;
            unsigned axis = jk - bin * 3u;

            float x  = __ldg(&xyz[(p0 + dp) * 3u + axis]);
            float dt = __ldg(&div_term[bin]);
            __sincosf(x * dt, &s[k], &c[k]);             // |ang| <= 1, ample precision
        }

#pragma unroll
        for (int k = 0; k < F4_PER_THREAD; ++k) {
            int g = base + k * THREADS;
            if (g < total_f4)
                __stcs(&out[g], make_float4(c[k], s[k], c[k], s[k]));
        }
    }
}

extern "C" void kernel_launch(void* const* d_in, const int* in_sizes, int n_in,
                              void* d_out, int out_size) {
    const float* xyz      = (const float*)d_in[0];
    const float* div_term = (const float*)d_in[1];
    float4* out = (float4*)d_out;

    int total_f4  = out_size / 4;                        // 25,165,824 for B=4, N=65536
    int num_tiles = (total_f4 + TILE - 1) / TILE;        // 24,576
    int blocks    = num_tiles < MAX_BLOCKS ? num_tiles : MAX_BLOCKS;  // 1,184
    rope3d_kernel<<<blocks, THREADS>>>(xyz, div_term, out, num_tiles, total_f4);
}

// round 12
// speedup vs baseline: 1.1465x; 1.1465x over previous
#include <cuda_runtime.h>
#include <cuda_bf16.h>

// RotaryPositionEncoding3D: out[B,N,192,2] f32 from xyz[B,N,3] f32 and div_term[32] f32.
// Each output float4 g = (cos, sin, cos, sin) of angle xyz[p, axis]*div_term[bin],
//   p = g/96, j = g%96, axis = j%3, bin = j/3.
//
// v8: v2 config (256 thr, 4 float4/thread, __stcs, 24576 exact-fit blocks) with
// WARP-CONTIGUOUS store ordering: each warp owns one contiguous 2KB block
//   g = blockStart + wid*128 + k*32 + lane            (k-stride 32, not 256)
// so its 4 STG.128s hit consecutive 512B chunks in address order, instead of
// v2's 4KB-apart chunks. Goal: sequential dirty-line drain per warp -> better
// DRAM row locality, independent of inter-warp scheduler timing.
// Index math stays closed-form/independent per k (t = j0 + 32k <= 191).
// 402.6 MB stored; v2 achieved 7.0 TB/s (88% of spec).

#define F4_PER_THREAD 4
#define THREADS 256
#define TILE (THREADS * F4_PER_THREAD)   // 1024 float4 per block

__global__ void __launch_bounds__(THREADS)
rope3d_kernel(const float* __restrict__ xyz,
              const float* __restrict__ div_term,
              float4* __restrict__ out,
              int total_f4) {
    const int wid  = (int)threadIdx.x >> 5;
    const int lane = (int)threadIdx.x & 31;
    // Warp's contiguous 2KB block: 4 chunks of 32 float4s
    const int base = blockIdx.x * TILE + wid * (F4_PER_THREAD * 32) + lane;

    const unsigned p0 = (unsigned)base / 96u;
    const unsigned j0 = (unsigned)base - p0 * 96u;   // [0, 96)

    float c[F4_PER_THREAD], s[F4_PER_THREAD];

#pragma unroll
    for (int k = 0; k < F4_PER_THREAD; ++k) {
        // Independent per-k index math: t = j0 + 32k <= 95 + 96 = 191
        unsigned t    = j0 + (unsigned)(k * 32);
        unsigned dp   = t / 96u;                     // 0 or 1 (range-limited)
        unsigned jk   = t - dp * 96u;                // j = 3*bin + axis
        unsigned bin  = jk / 3u;
        unsigned axis = jk - bin * 3u;

        float x  = __ldg(&xyz[(p0 + dp) * 3u + axis]);
        float dt = __ldg(&div_term[bin]);
        __sincosf(x * dt, &s[k], &c[k]);             // |ang| <= 1, ample precision
    }

#pragma unroll
    for (int k = 0; k < F4_PER_THREAD; ++k) {
        int g = base + k * 32;
        if (g < total_f4)
            __stcs(&out[g], make_float4(c[k], s[k], c[k], s[k]));
    }
}

extern "C" void kernel_launch(void* const* d_in, const int* in_sizes, int n_in,
                              void* d_out, int out_size) {
    const float* xyz      = (const float*)d_in[0];
    const float* div_term = (const float*)d_in[1];
    float4* out = (float4*)d_out;

    int total_f4 = out_size / 4;                     // 25,165,824 for B=4, N=65536
    int blocks = (total_f4 + TILE - 1) / TILE;       // 24,576 (exact fit)
    rope3d_kernel<<<blocks, THREADS>>>(xyz, div_term, out, total_f4);
}